// round 12
// baseline (speedup 1.0000x reference)
#include <cuda_runtime.h>
#include <cuda_fp16.h>

// TrilinearInterpolation, single-launch, CTA-specialized, LDG-pipelined.
// d_out = [lut passthrough (107811 f32)][out (32,3,512,512) f32].
//
// CTAs [0, n1)    : smem = half2(ch0[i], ch1[i])       8 LDS/px, ch0+ch1, U1=2
// CTAs [n1, grid) : smem = half2(c2[i], c2[i+1]-c2[i]) 4 LDS/px, ch2,     U2=4
// Each CTA converts fp32->fp16 while staging (no separate cvt kernel), and
// the fp32 LUT passthrough is grid-strided into the same kernel.
// Image loads for block i+1 are prefetched before processing block i:
// R11's profile showed ~600-cyc LDG latency exposed once per iteration
// (the 21% gap between L1-busy and duration).

constexpr int D   = 33;
constexpr int DD  = D * D;          // 1089
constexpr int D3  = D * D * D;      // 35937
constexpr int HW  = 512 * 512;      // 262144
constexpr int NPX = 32 * HW;        // 8388608
constexpr int SMEM_BYTES = D3 * 4;  // 143748
constexpr int BLK = 1024;

constexpr int U1 = 2;
constexpr int STEP1 = BLK * U1;         // 2048 (divides HW)
constexpr int NB1   = NPX / STEP1;      // 4096

constexpr int U2 = 4;
constexpr int STEP2 = BLK * U2;         // 4096 (divides HW)
constexpr int NB2   = NPX / STEP2;      // 2048

__device__ __forceinline__ void coords(float r, float g, float b,
                                       int& base, float& wx, float& wy, float& wz)
{
    const float S = 32.0f, S1 = 31.0f;
    float x = fminf(fmaxf(r * S, 0.0f), S);
    float y = fminf(fmaxf(g * S, 0.0f), S);
    float z = fminf(fmaxf(b * S, 0.0f), S);
    float x0 = fminf(floorf(x), S1);
    float y0 = fminf(floorf(y), S1);
    float z0 = fminf(floorf(z), S1);
    wx = x - x0; wy = y - y0; wz = z - z0;
    base = (int)z0 * DD + (int)y0 * D + (int)x0;
}

struct Px1 { float r[U1], g[U1], b[U1]; };
struct Px2 { float r[U2], g[U2], b[U2]; };

__device__ __forceinline__ Px1 load1(const float* __restrict__ img, int blk, int tid)
{
    Px1 p;
    const int px0 = blk * STEP1;
    const int ib  = ((px0 >> 18) * 3) << 18;
    const int hw0 = (px0 & (HW - 1)) + tid;
    #pragma unroll
    for (int k = 0; k < U1; ++k) {
        int hw = hw0 + k * BLK;
        p.r[k] = __ldg(img + ib + hw);
        p.g[k] = __ldg(img + ib + HW + hw);
        p.b[k] = __ldg(img + ib + 2 * HW + hw);
    }
    return p;
}

__device__ __forceinline__ Px2 load2(const float* __restrict__ img, int blk, int tid)
{
    Px2 p;
    const int px0 = blk * STEP2;
    const int ib  = ((px0 >> 18) * 3) << 18;
    const int hw0 = (px0 & (HW - 1)) + tid;
    #pragma unroll
    for (int k = 0; k < U2; ++k) {
        int hw = hw0 + k * BLK;
        p.r[k] = __ldg(img + ib + hw);
        p.g[k] = __ldg(img + ib + HW + hw);
        p.b[k] = __ldg(img + ib + 2 * HW + hw);
    }
    return p;
}

__device__ __forceinline__ void proc1(const __half2* __restrict__ st,
                                      float* __restrict__ out,
                                      int blk, int tid, const Px1& p)
{
    const int px0 = blk * STEP1;
    const int ib  = ((px0 >> 18) * 3) << 18;
    const int hw0 = (px0 & (HW - 1)) + tid;
    #pragma unroll
    for (int k = 0; k < U1; ++k) {
        int base; float wx, wy, wz;
        coords(p.r[k], p.g[k], p.b[k], base, wx, wy, wz);

        float2 p000 = __half22float2(st[base]);
        float2 p001 = __half22float2(st[base + 1]);
        float2 p010 = __half22float2(st[base + D]);
        float2 p011 = __half22float2(st[base + D + 1]);
        float2 p100 = __half22float2(st[base + DD]);
        float2 p101 = __half22float2(st[base + DD + 1]);
        float2 p110 = __half22float2(st[base + DD + D]);
        float2 p111 = __half22float2(st[base + DD + D + 1]);

        float a00 = fmaf(wx, p001.x - p000.x, p000.x);
        float a01 = fmaf(wx, p011.x - p010.x, p010.x);
        float a10 = fmaf(wx, p101.x - p100.x, p100.x);
        float a11 = fmaf(wx, p111.x - p110.x, p110.x);
        float b0  = fmaf(wy, a01 - a00, a00);
        float b1  = fmaf(wy, a11 - a10, a10);
        float r0  = fmaf(wz, b1 - b0, b0);

        a00 = fmaf(wx, p001.y - p000.y, p000.y);
        a01 = fmaf(wx, p011.y - p010.y, p010.y);
        a10 = fmaf(wx, p101.y - p100.y, p100.y);
        a11 = fmaf(wx, p111.y - p110.y, p110.y);
        b0  = fmaf(wy, a01 - a00, a00);
        b1  = fmaf(wy, a11 - a10, a10);
        float r1 = fmaf(wz, b1 - b0, b0);

        int hw = hw0 + k * BLK;
        __stcs(out + ib + hw, r0);             // c=0 plane
        __stcs(out + ib + HW + hw, r1);        // c=1 plane
    }
}

__device__ __forceinline__ void proc2(const __half2* __restrict__ st,
                                      float* __restrict__ out,
                                      int blk, int tid, const Px2& p)
{
    const int px0 = blk * STEP2;
    const int ib  = ((px0 >> 18) * 3) << 18;
    const int hw0 = (px0 & (HW - 1)) + tid;
    #pragma unroll
    for (int k = 0; k < U2; ++k) {
        int base; float wx, wy, wz;
        coords(p.r[k], p.g[k], p.b[k], base, wx, wy, wz);

        float2 e00 = __half22float2(st[base]);          // (v, v_next - v)
        float2 e01 = __half22float2(st[base + D]);
        float2 e10 = __half22float2(st[base + DD]);
        float2 e11 = __half22float2(st[base + DD + D]);

        float a00 = fmaf(wx, e00.y, e00.x);
        float a01 = fmaf(wx, e01.y, e01.x);
        float a10 = fmaf(wx, e10.y, e10.x);
        float a11 = fmaf(wx, e11.y, e11.x);
        float b0  = fmaf(wy, a01 - a00, a00);
        float b1  = fmaf(wy, a11 - a10, a10);

        int hw = hw0 + k * BLK;
        __stcs(out + ib + 2 * HW + hw, fmaf(wz, b1 - b0, b0));  // c=2
    }
}

__global__ __launch_bounds__(BLK, 1)
void trilerp_kernel(const float* __restrict__ lut,
                    const float* __restrict__ img,
                    float* __restrict__ out_full)   // = d_out (tuple base)
{
    extern __shared__ unsigned int sm[];
    const int tid = threadIdx.x;
    const int n1  = ((int)gridDim.x * 129) / 200;   // 98 of 152
    const bool is01 = (int)blockIdx.x < n1;
    float* out = out_full + 3 * D3;                 // trilerp output region

    // LUT passthrough (grid-strided; ~0.7 elements/thread).
    for (int j = blockIdx.x * BLK + tid; j < 3 * D3; j += (int)gridDim.x * BLK)
        out_full[j] = __ldg(lut + j);

    // Stage + convert this group's table directly from the fp32 LUT.
    if (is01) {
        for (int i = tid; i < D3; i += BLK) {
            __half2 h = __floats2half2_rn(__ldg(lut + i), __ldg(lut + D3 + i));
            sm[i] = *reinterpret_cast<unsigned int*>(&h);
        }
    } else {
        for (int i = tid; i < D3; i += BLK) {
            float v  = __ldg(lut + 2 * D3 + i);
            float vn = (i + 1 < D3) ? __ldg(lut + 2 * D3 + i + 1) : v;
            __half2 h = __floats2half2_rn(v, vn - v);
            sm[i] = *reinterpret_cast<unsigned int*>(&h);
        }
    }
    __syncthreads();
    const __half2* st = reinterpret_cast<const __half2*>(sm);

    if (is01) {
        int blk = blockIdx.x;
        if (blk < NB1) {
            Px1 cur = load1(img, blk, tid);
            int nxt = blk + n1;
            while (nxt < NB1) {
                Px1 pre = load1(img, nxt, tid);   // prefetch next block
                proc1(st, out, blk, tid, cur);    // process current
                cur = pre;
                blk = nxt;
                nxt += n1;
            }
            proc1(st, out, blk, tid, cur);
        }
    } else {
        const int n2 = (int)gridDim.x - n1;
        int blk = blockIdx.x - n1;
        if (blk < NB2) {
            Px2 cur = load2(img, blk, tid);
            int nxt = blk + n2;
            while (nxt < NB2) {
                Px2 pre = load2(img, nxt, tid);
                proc2(st, out, blk, tid, cur);
                cur = pre;
                blk = nxt;
                nxt += n2;
            }
            proc2(st, out, blk, tid, cur);
        }
    }
}

extern "C" void kernel_launch(void* const* d_in, const int* in_sizes, int n_in,
                              void* d_out, int out_size)
{
    const float* lut = (const float*)d_in[0];
    const float* img = (const float*)d_in[1];
    if (n_in >= 2 && in_sizes[0] > in_sizes[1]) {   // defensive input-order check
        lut = (const float*)d_in[1];
        img = (const float*)d_in[0];
    }
    float* out = (float*)d_out;

    cudaFuncSetAttribute(trilerp_kernel,
                         cudaFuncAttributeMaxDynamicSharedMemorySize, SMEM_BYTES);

    int sms = 148;
    cudaDeviceGetAttribute(&sms, cudaDevAttrMultiProcessorCount, 0);

    trilerp_kernel<<<sms, BLK, SMEM_BYTES>>>(lut, img, out);
}

// round 13
// speedup vs baseline: 1.0659x; 1.0659x over previous
#include <cuda_runtime.h>
#include <cuda_fp16.h>

// TrilinearInterpolation, single-launch, CTA-specialized, LDG+LDS pipelined.
// d_out = [lut passthrough (107811 f32)][out (32,3,512,512) f32].
//
// CTAs [0, n1)    : smem = half2(ch0[i], ch1[i])       8 LDS/px, ch0+ch1, U1=2
// CTAs [n1, grid) : smem = half2(c2[i], c2[i+1]-c2[i]) 4 LDS/px, ch2,     U2=4
// R12 profile: L1 busy (47us) == computed wavefront floor; remaining time is
// duty-cycle loss. This round: (a) batch ALL LDS of an iteration after ALL
// coords (2x smem-MLP per warp), (b) cheap coords (saturate + trunc),
// (c) unrolled staging. Numerics identical to R12.

constexpr int D   = 33;
constexpr int DD  = D * D;          // 1089
constexpr int D3  = D * D * D;      // 35937
constexpr int HW  = 512 * 512;      // 262144
constexpr int NPX = 32 * HW;        // 8388608
constexpr int SMEM_BYTES = D3 * 4;  // 143748
constexpr int BLK = 1024;

constexpr int U1 = 2;
constexpr int STEP1 = BLK * U1;         // 2048 (divides HW)
constexpr int NB1   = NPX / STEP1;      // 4096

constexpr int U2 = 4;
constexpr int STEP2 = BLK * U2;         // 4096 (divides HW)
constexpr int NB2   = NPX / STEP2;      // 2048

// Exact-equivalent of reference clip/floor for r>=0 inputs:
// x = clip(r*32,0,32); x0 = clip(floor(x),0,31); w = x-x0.
__device__ __forceinline__ void coords(float r, float g, float b,
                                       int& base, float& wx, float& wy, float& wz)
{
    float x = __saturatef(r) * 32.0f;
    float y = __saturatef(g) * 32.0f;
    float z = __saturatef(b) * 32.0f;
    int ix = min((int)x, 31);           // trunc == floor (x >= 0)
    int iy = min((int)y, 31);
    int iz = min((int)z, 31);
    wx = x - (float)ix;
    wy = y - (float)iy;
    wz = z - (float)iz;
    base = iz * DD + iy * D + ix;
}

struct Px1 { float r[U1], g[U1], b[U1]; };
struct Px2 { float r[U2], g[U2], b[U2]; };

__device__ __forceinline__ Px1 load1(const float* __restrict__ img, int blk, int tid)
{
    Px1 p;
    const int px0 = blk * STEP1;
    const int ib  = ((px0 >> 18) * 3) << 18;
    const int hw0 = (px0 & (HW - 1)) + tid;
    #pragma unroll
    for (int k = 0; k < U1; ++k) {
        int hw = hw0 + k * BLK;
        p.r[k] = __ldg(img + ib + hw);
        p.g[k] = __ldg(img + ib + HW + hw);
        p.b[k] = __ldg(img + ib + 2 * HW + hw);
    }
    return p;
}

__device__ __forceinline__ Px2 load2(const float* __restrict__ img, int blk, int tid)
{
    Px2 p;
    const int px0 = blk * STEP2;
    const int ib  = ((px0 >> 18) * 3) << 18;
    const int hw0 = (px0 & (HW - 1)) + tid;
    #pragma unroll
    for (int k = 0; k < U2; ++k) {
        int hw = hw0 + k * BLK;
        p.r[k] = __ldg(img + ib + hw);
        p.g[k] = __ldg(img + ib + HW + hw);
        p.b[k] = __ldg(img + ib + 2 * HW + hw);
    }
    return p;
}

__device__ __forceinline__ void proc1(const __half2* __restrict__ st,
                                      float* __restrict__ out,
                                      int blk, int tid, const Px1& p)
{
    const int px0 = blk * STEP1;
    const int ib  = ((px0 >> 18) * 3) << 18;
    const int hw0 = (px0 & (HW - 1)) + tid;

    // Phase A: all coords.
    int base[U1]; float wx[U1], wy[U1], wz[U1];
    #pragma unroll
    for (int k = 0; k < U1; ++k)
        coords(p.r[k], p.g[k], p.b[k], base[k], wx[k], wy[k], wz[k]);

    // Phase B: all 16 LDS issued back-to-back (max smem-MLP).
    __half2 q[U1][8];
    #pragma unroll
    for (int k = 0; k < U1; ++k) {
        int bse = base[k];
        q[k][0] = st[bse];          q[k][1] = st[bse + 1];
        q[k][2] = st[bse + D];      q[k][3] = st[bse + D + 1];
        q[k][4] = st[bse + DD];     q[k][5] = st[bse + DD + 1];
        q[k][6] = st[bse + DD + D]; q[k][7] = st[bse + DD + D + 1];
    }

    // Phase C: math + stores.
    #pragma unroll
    for (int k = 0; k < U1; ++k) {
        float2 p000 = __half22float2(q[k][0]);
        float2 p001 = __half22float2(q[k][1]);
        float2 p010 = __half22float2(q[k][2]);
        float2 p011 = __half22float2(q[k][3]);
        float2 p100 = __half22float2(q[k][4]);
        float2 p101 = __half22float2(q[k][5]);
        float2 p110 = __half22float2(q[k][6]);
        float2 p111 = __half22float2(q[k][7]);

        float a00 = fmaf(wx[k], p001.x - p000.x, p000.x);
        float a01 = fmaf(wx[k], p011.x - p010.x, p010.x);
        float a10 = fmaf(wx[k], p101.x - p100.x, p100.x);
        float a11 = fmaf(wx[k], p111.x - p110.x, p110.x);
        float b0  = fmaf(wy[k], a01 - a00, a00);
        float b1  = fmaf(wy[k], a11 - a10, a10);
        float r0  = fmaf(wz[k], b1 - b0, b0);

        a00 = fmaf(wx[k], p001.y - p000.y, p000.y);
        a01 = fmaf(wx[k], p011.y - p010.y, p010.y);
        a10 = fmaf(wx[k], p101.y - p100.y, p100.y);
        a11 = fmaf(wx[k], p111.y - p110.y, p110.y);
        b0  = fmaf(wy[k], a01 - a00, a00);
        b1  = fmaf(wy[k], a11 - a10, a10);
        float r1 = fmaf(wz[k], b1 - b0, b0);

        int hw = hw0 + k * BLK;
        __stcs(out + ib + hw, r0);             // c=0 plane
        __stcs(out + ib + HW + hw, r1);        // c=1 plane
    }
}

__device__ __forceinline__ void proc2(const __half2* __restrict__ st,
                                      float* __restrict__ out,
                                      int blk, int tid, const Px2& p)
{
    const int px0 = blk * STEP2;
    const int ib  = ((px0 >> 18) * 3) << 18;
    const int hw0 = (px0 & (HW - 1)) + tid;

    // Two sub-batches of 2 px (8 LDS in flight each) to stay in registers.
    #pragma unroll
    for (int h = 0; h < U2 / 2; ++h) {
        int base[2]; float wx[2], wy[2], wz[2];
        #pragma unroll
        for (int j = 0; j < 2; ++j) {
            int k = h * 2 + j;
            coords(p.r[k], p.g[k], p.b[k], base[j], wx[j], wy[j], wz[j]);
        }
        __half2 q[2][4];
        #pragma unroll
        for (int j = 0; j < 2; ++j) {
            int bse = base[j];
            q[j][0] = st[bse];          // (v, v_next - v)
            q[j][1] = st[bse + D];
            q[j][2] = st[bse + DD];
            q[j][3] = st[bse + DD + D];
        }
        #pragma unroll
        for (int j = 0; j < 2; ++j) {
            float2 e00 = __half22float2(q[j][0]);
            float2 e01 = __half22float2(q[j][1]);
            float2 e10 = __half22float2(q[j][2]);
            float2 e11 = __half22float2(q[j][3]);

            float a00 = fmaf(wx[j], e00.y, e00.x);
            float a01 = fmaf(wx[j], e01.y, e01.x);
            float a10 = fmaf(wx[j], e10.y, e10.x);
            float a11 = fmaf(wx[j], e11.y, e11.x);
            float b0  = fmaf(wy[j], a01 - a00, a00);
            float b1  = fmaf(wy[j], a11 - a10, a10);

            int hw = hw0 + (h * 2 + j) * BLK;
            __stcs(out + ib + 2 * HW + hw, fmaf(wz[j], b1 - b0, b0));  // c=2
        }
    }
}

__global__ __launch_bounds__(BLK, 1)
void trilerp_kernel(const float* __restrict__ lut,
                    const float* __restrict__ img,
                    float* __restrict__ out_full)   // = d_out (tuple base)
{
    extern __shared__ unsigned int sm[];
    const int tid = threadIdx.x;
    const int n1  = ((int)gridDim.x * 129) / 200;   // 98 of 152
    const bool is01 = (int)blockIdx.x < n1;
    float* out = out_full + 3 * D3;                 // trilerp output region

    // LUT passthrough (grid-strided; ~0.7 elements/thread).
    for (int j = blockIdx.x * BLK + tid; j < 3 * D3; j += (int)gridDim.x * BLK)
        out_full[j] = __ldg(lut + j);

    // Stage + convert this group's table directly from the fp32 LUT.
    if (is01) {
        #pragma unroll 4
        for (int i = tid; i < D3; i += BLK) {
            __half2 h = __floats2half2_rn(__ldg(lut + i), __ldg(lut + D3 + i));
            sm[i] = *reinterpret_cast<unsigned int*>(&h);
        }
    } else {
        #pragma unroll 4
        for (int i = tid; i < D3; i += BLK) {
            float v  = __ldg(lut + 2 * D3 + i);
            float vn = (i + 1 < D3) ? __ldg(lut + 2 * D3 + i + 1) : v;
            __half2 h = __floats2half2_rn(v, vn - v);
            sm[i] = *reinterpret_cast<unsigned int*>(&h);
        }
    }
    __syncthreads();
    const __half2* st = reinterpret_cast<const __half2*>(sm);

    if (is01) {
        int blk = blockIdx.x;
        if (blk < NB1) {
            Px1 cur = load1(img, blk, tid);
            int nxt = blk + n1;
            while (nxt < NB1) {
                Px1 pre = load1(img, nxt, tid);   // prefetch next block
                proc1(st, out, blk, tid, cur);    // process current
                cur = pre;
                blk = nxt;
                nxt += n1;
            }
            proc1(st, out, blk, tid, cur);
        }
    } else {
        const int n2 = (int)gridDim.x - n1;
        int blk = blockIdx.x - n1;
        if (blk < NB2) {
            Px2 cur = load2(img, blk, tid);
            int nxt = blk + n2;
            while (nxt < NB2) {
                Px2 pre = load2(img, nxt, tid);
                proc2(st, out, blk, tid, cur);
                cur = pre;
                blk = nxt;
                nxt += n2;
            }
            proc2(st, out, blk, tid, cur);
        }
    }
}

extern "C" void kernel_launch(void* const* d_in, const int* in_sizes, int n_in,
                              void* d_out, int out_size)
{
    const float* lut = (const float*)d_in[0];
    const float* img = (const float*)d_in[1];
    if (n_in >= 2 && in_sizes[0] > in_sizes[1]) {   // defensive input-order check
        lut = (const float*)d_in[1];
        img = (const float*)d_in[0];
    }
    float* out = (float*)d_out;

    cudaFuncSetAttribute(trilerp_kernel,
                         cudaFuncAttributeMaxDynamicSharedMemorySize, SMEM_BYTES);

    int sms = 148;
    cudaDeviceGetAttribute(&sms, cudaDevAttrMultiProcessorCount, 0);

    trilerp_kernel<<<sms, BLK, SMEM_BYTES>>>(lut, img, out);
}